// round 14
// baseline (speedup 1.0000x reference)
#include <cuda_runtime.h>
#include <cuda_bf16.h>
#include <math.h>

#define BQ 2
#define S_LEN 2048
#define HK 16
#define HV 32
#define DK 128
#define DV 128
#define QKV 8192
#define NROWS (BQ * S_LEN)
#define TB 16   // tokens per smem staging batch (rec); 8 pairs

typedef unsigned long long ull;

// ---------------- scratch (device globals; no runtime allocation) ----------------
__device__ float g_qn[(size_t)NROWS * HK * DK];    // l2norm(q) * scale
__device__ float g_kn[(size_t)NROWS * HK * DK];    // l2norm(k)
__device__ float g_v [(size_t)NROWS * HV * DV];
__device__ float g_gate[(size_t)NROWS * HV * 2];   // float2 per (row,h): eg, beta
__device__ float2 g_cross[(size_t)BQ * (S_LEN / 2) * HK];  // per (b,tp,hk): (k1.k2, q1.k1)

// ---------------- packed f32x2 helpers ----------------
__device__ __forceinline__ ull pack2(float lo, float hi) {
    ull r;
    asm("mov.b64 %0, {%1,%2};" : "=l"(r) : "f"(lo), "f"(hi));
    return r;
}
__device__ __forceinline__ float2 unpack2(ull v) {
    float2 r;
    asm("mov.b64 {%0,%1}, %2;" : "=f"(r.x), "=f"(r.y) : "l"(v));
    return r;
}
__device__ __forceinline__ float sum2(ull v) {
    float2 r = unpack2(v);
    return r.x + r.y;
}
#define FMA2(d, a, b, c) asm("fma.rn.f32x2 %0, %1, %2, %3;" : "=l"(d) : "l"(a), "l"(b), "l"(c))
#define MUL2(d, a, b)    asm("mul.rn.f32x2 %0, %1, %2;"     : "=l"(d) : "l"(a), "l"(b))
#define ADD2(d, a, b)    asm("add.rn.f32x2 %0, %1, %2;"     : "=l"(d) : "l"(a), "l"(b))

union F4U { float4 f; ull u[2]; };

// ---------------- cp.async helpers ----------------
__device__ __forceinline__ void cpa16(void* smem, const void* gmem) {
    unsigned s = (unsigned)__cvta_generic_to_shared(smem);
    asm volatile("cp.async.cg.shared.global [%0], [%1], 16;" :: "r"(s), "l"(gmem));
}
__device__ __forceinline__ void cpa8(void* smem, const void* gmem) {
    unsigned s = (unsigned)__cvta_generic_to_shared(smem);
    asm volatile("cp.async.ca.shared.global [%0], [%1], 8;" :: "r"(s), "l"(gmem));
}
__device__ __forceinline__ void cpa_commit() {
    asm volatile("cp.async.commit_group;" ::: "memory");
}
__device__ __forceinline__ void cpa_wait0() {
    asm volatile("cp.async.wait_group 0;" ::: "memory");
}

// ---------------- kernel 1: register sliding-window conv + silu + l2norm ----------------
__global__ __launch_bounds__(256) void prep_kernel(
    const float* __restrict__ x,      // [NROWS, QKV]
    const float* __restrict__ w)      // [QKV, 4]
{
    const int gw   = (blockIdx.x * 256 + threadIdx.x) >> 5;
    const int lane = threadIdx.x & 31;
    const int strip = gw & 127;
    const int hb    = (gw >> 7) & 63;
    const int b     = gw >> 13;
    const int t0    = strip * 16;
    const int ch    = hb * 128 + lane * 4;

    const float* xp = x + (size_t)(b * S_LEN + t0) * QKV + ch;

    const float4* w4 = (const float4*)w;
    const float4 wv0 = __ldg(w4 + ch + 0);
    const float4 wv1 = __ldg(w4 + ch + 1);
    const float4 wv2 = __ldg(w4 + ch + 2);
    const float4 wv3 = __ldg(w4 + ch + 3);

    float4 h0 = make_float4(0.f, 0.f, 0.f, 0.f);
    float4 h1 = h0, h2 = h0;
    if (t0 >= 3) {
        h0 = *reinterpret_cast<const float4*>(xp - 3 * QKV);
        h1 = *reinterpret_cast<const float4*>(xp - 2 * QKV);
        h2 = *reinterpret_cast<const float4*>(xp - 1 * QKV);
    }

    const float qscale = 0.08838834764831845f;

#define CONV_STEP(a, T) do {                                                        \
    const float4 xc = *reinterpret_cast<const float4*>(xp + (size_t)(T) * QKV);    \
    a.x = fmaf(h0.x, wv0.x, fmaf(h1.x, wv0.y, fmaf(h2.x, wv0.z, xc.x * wv0.w)));   \
    a.y = fmaf(h0.y, wv1.x, fmaf(h1.y, wv1.y, fmaf(h2.y, wv1.z, xc.y * wv1.w)));   \
    a.z = fmaf(h0.z, wv2.x, fmaf(h1.z, wv2.y, fmaf(h2.z, wv2.z, xc.z * wv2.w)));   \
    a.w = fmaf(h0.w, wv3.x, fmaf(h1.w, wv3.y, fmaf(h2.w, wv3.z, xc.w * wv3.w)));   \
    a.x = a.x / (1.f + __expf(-a.x));                                              \
    a.y = a.y / (1.f + __expf(-a.y));                                              \
    a.z = a.z / (1.f + __expf(-a.z));                                              \
    a.w = a.w / (1.f + __expf(-a.w));                                              \
    h0 = h1; h1 = h2; h2 = xc;                                                     \
} while (0)

    if (hb < 32) {
        const bool isq = hb < 16;
        const int head = isq ? hb : hb - 16;
        float* dbase = (isq ? g_qn : g_kn)
                     + ((size_t)(b * S_LEN + t0) * HK + head) * DK + lane * 4;
        const float sc = isq ? qscale : 1.f;
#pragma unroll
        for (int t = 0; t < 16; t++) {
            float4 a;
            CONV_STEP(a, t);
            float ss = a.x * a.x + a.y * a.y + a.z * a.z + a.w * a.w;
#pragma unroll
            for (int o = 16; o > 0; o >>= 1)
                ss += __shfl_xor_sync(0xffffffffu, ss, o);
            const float mul = rsqrtf(ss + 1e-6f) * sc;
            a.x *= mul; a.y *= mul; a.z *= mul; a.w *= mul;
            *reinterpret_cast<float4*>(dbase + (size_t)t * (HK * DK)) = a;
        }
    } else {
        const int head = hb - 32;
        float* dbase = g_v + ((size_t)(b * S_LEN + t0) * HV + head) * DV + lane * 4;
#pragma unroll
        for (int t = 0; t < 16; t++) {
            float4 a;
            CONV_STEP(a, t);
            *reinterpret_cast<float4*>(dbase + (size_t)t * (HV * DV)) = a;
        }
    }
#undef CONV_STEP
}

// ---------------- kernel 1b: gating ----------------
__global__ __launch_bounds__(256) void gate_kernel(
    const float* __restrict__ bvec,
    const float* __restrict__ avec,
    const float* __restrict__ dt_bias,
    const float* __restrict__ alog)
{
    const int idx = blockIdx.x * 256 + threadIdx.x;
    const int h = idx & 31;
    float aa = avec[idx] + __ldg(dt_bias + h);
    float sp = (aa > 20.f) ? aa : log1pf(expf(aa));
    float g  = -expf(__ldg(alog + h)) * sp;
    float eg = expf(g);
    float bb = bvec[idx];
    float beta = 1.f / (1.f + expf(-bb));
    *reinterpret_cast<float2*>(g_gate + (size_t)idx * 2) = make_float2(eg, beta);
}

// ---------------- kernel 1c: pair cross-scalars (k1.k2, q1.k1) ----------------
__global__ __launch_bounds__(256) void cross_kernel()
{
    const int gw   = blockIdx.x * 8 + (threadIdx.x >> 5);   // 32768 warps
    const int lane = threadIdx.x & 31;
    const int b  = gw >> 14;
    const int hk = (gw >> 10) & 15;
    const int tp = gw & 1023;

    const size_t base = ((size_t)(b * S_LEN + 2 * tp) * HK + hk) * DK + lane * 4;
    const float4 k1 = *reinterpret_cast<const float4*>(g_kn + base);
    const float4 k2 = *reinterpret_cast<const float4*>(g_kn + base + HK * DK);
    const float4 q1 = *reinterpret_cast<const float4*>(g_qn + base);

    float ck = k1.x * k2.x + k1.y * k2.y + k1.z * k2.z + k1.w * k2.w;
    float qk = q1.x * k1.x + q1.y * k1.y + q1.z * k1.z + q1.w * k1.w;
#pragma unroll
    for (int o = 16; o > 0; o >>= 1) {
        ck += __shfl_xor_sync(0xffffffffu, ck, o);
        qk += __shfl_xor_sync(0xffffffffu, qk, o);
    }
    if (lane == 0)
        g_cross[(size_t)(b * (S_LEN / 2) + tp) * HK + hk] = make_float2(ck, qk);
}

// ---------------- kernel 2: rank-2 gated delta-rule, 512 threads ----------------
// grid 128 = (b, h, vh). 512 threads = 32 column-pairs x 16 k-slices of 8 dims.
// Thread (c2, p): state 8 dims x 2 cols (owned so[4], other sx[4] as f32x2).
// 16 warps/SM = 4/SMSP (vs 2 before) at ~invariant total instructions -> issue%.
// k/q rows stored 2-plane: plane q holds gmem float4 chunks (2p+q) at slot p;
// LDS.128 by lane p at plane+16B*p is conflict-free per 8-lane phase.
// Reduction: owner-split fold (xor 8) + tree (1,2,4); chains Pa,Pb,G1,prev-oo
// interleaved in one burst. u/coeff exchange via xor 8. o2 deferred one pair.
__global__ __launch_bounds__(512, 1) void rec_kernel(float* __restrict__ out)
{
    const int blk = blockIdx.x;
    const int b   = blk >> 6;
    const int h   = (blk >> 1) & 31;
    const int vh  = blk & 1;
    const int hk  = h >> 1;

    const int tid = threadIdx.x;
    const int c2  = tid >> 4;          // column pair 0..31
    const int p   = tid & 15;          // k-slice 0..15 (8 dims)
    const bool lowp = (p < 8);

    __shared__ float sk[2][TB][128];   // 2-plane per token
    __shared__ float sq[2][TB][128];
    __shared__ float sv[2][TB][64];
    __shared__ float2 sg[2][TB];
    __shared__ float2 scr[2][TB / 2];

    ull so[4], sx[4];                  // owned / other column state (8 dims)
#pragma unroll
    for (int i = 0; i < 4; i++) { so[i] = 0ull; sx[i] = 0ull; }

    const float* kbase = g_kn + ((size_t)(b * S_LEN) * HK + hk) * DK;
    const float* qbase = g_qn + ((size_t)(b * S_LEN) * HK + hk) * DK;
    const float* vbase = g_v  + ((size_t)(b * S_LEN) * HV + h) * DV + vh * 64;
    const float* gbase = g_gate + ((size_t)(b * S_LEN) * HV + h) * 2;
    const size_t qk_stride = (size_t)HK * DK;
    const size_t v_stride  = (size_t)HV * DV;

    auto load_batch = [&](int buf, int t0) {
        // k and q: 16 tok x 32 chunks = 512 each -> 1 round each
        {
            int tt = tid >> 5, j = tid & 31;
            int dst = (j & 1) * 64 + (j >> 1) * 4;
            cpa16(&sk[buf][tt][dst], kbase + (size_t)(t0 + tt) * qk_stride + j * 4);
            cpa16(&sq[buf][tt][dst], qbase + (size_t)(t0 + tt) * qk_stride + j * 4);
        }
        if (tid < 256) {
            int tt = tid >> 4, j = tid & 15;
            cpa16(&sv[buf][tt][j * 4], vbase + (size_t)(t0 + tt) * v_stride + j * 4);
        }
        if (tid < TB)
            cpa8(&sg[buf][tid], gbase + (size_t)(t0 + tid) * (HV * 2));
        if (tid < TB / 2)
            cpa8(&scr[buf][tid],
                 &g_cross[(size_t)(b * (S_LEN / 2) + (t0 >> 1) + tid) * HK + hk]);
        cpa_commit();
    };

    load_batch(0, 0);
    cpa_wait0();
    __syncthreads();
    int buf = 0;

    float* obase = out + ((size_t)(b * S_LEN) * HV + h) * DV + vh * 64 + c2 * 2;
    const int osel = lowp ? 0 : 1;

    float oo_m = 0.f, oo_o = 0.f;      // prev token's o2 partials (own/other)

#pragma unroll 1
    for (int t0 = 0; t0 < S_LEN; t0 += TB) {
        if (t0 + TB < S_LEN) load_batch(buf ^ 1, t0 + TB);

#pragma unroll 2
        for (int pp = 0; pp < TB / 2; pp++) {
            const int T = t0 + 2 * pp;
            const int s1 = 2 * pp, s2 = 2 * pp + 1;

            const float2 ga = sg[buf][s1];
            const float2 gb = sg[buf][s2];
            const float e1 = ga.x, b1 = ga.y, e2 = gb.x, b2 = gb.y;
            const float2 cr = scr[buf][pp];

            // slices: 8 floats = 2 float4 from the two planes
            F4U k1a, k1b, k2a, k2b, q1a, q1b;
            {
                const float* r1 = &sk[buf][s1][0];
                const float* r2 = &sk[buf][s2][0];
                const float* r3 = &sq[buf][s1][0];
                k1a.f = *reinterpret_cast<const float4*>(r1 + p * 4);
                k1b.f = *reinterpret_cast<const float4*>(r1 + 64 + p * 4);
                k2a.f = *reinterpret_cast<const float4*>(r2 + p * 4);
                k2b.f = *reinterpret_cast<const float4*>(r2 + 64 + p * 4);
                q1a.f = *reinterpret_cast<const float4*>(r3 + p * 4);
                q1b.f = *reinterpret_cast<const float4*>(r3 + 64 + p * 4);
            }

            // 6 dots (k1,k2,q1) x (so,sx), each depth-4 FMA2
            ull A = 0, B = 0, C = 0, D = 0, E = 0, F = 0;
            FMA2(A, k1a.u[0], so[0], A); FMA2(D, k1a.u[0], sx[0], D);
            FMA2(B, k2a.u[0], so[0], B); FMA2(E, k2a.u[0], sx[0], E);
            FMA2(C, q1a.u[0], so[0], C); FMA2(F, q1a.u[0], sx[0], F);
            FMA2(A, k1a.u[1], so[1], A); FMA2(D, k1a.u[1], sx[1], D);
            FMA2(B, k2a.u[1], so[1], B); FMA2(E, k2a.u[1], sx[1], E);
            FMA2(C, q1a.u[1], so[1], C); FMA2(F, q1a.u[1], sx[1], F);
            FMA2(A, k1b.u[0], so[2], A); FMA2(D, k1b.u[0], sx[2], D);
            FMA2(B, k2b.u[0], so[2], B); FMA2(E, k2b.u[0], sx[2], E);
            FMA2(C, q1b.u[0], so[2], C); FMA2(F, q1b.u[0], sx[2], F);
            FMA2(A, k1b.u[1], so[3], A); FMA2(D, k1b.u[1], sx[3], D);
            FMA2(B, k2b.u[1], so[3], B); FMA2(E, k2b.u[1], sx[3], E);
            FMA2(C, q1b.u[1], so[3], C); FMA2(F, q1b.u[1], sx[3], F);

            float Pam = sum2(A), Pbm = sum2(B), G1m = sum2(C);
            const float PaO = sum2(D), PbO = sum2(E), G1O = sum2(F);

            // ONE burst: fold other-col via xor 8, then tree 1,2,4; 4 chains
            Pam  += __shfl_xor_sync(0xffffffffu, PaO,  8);
            Pbm  += __shfl_xor_sync(0xffffffffu, PbO,  8);
            G1m  += __shfl_xor_sync(0xffffffffu, G1O,  8);
            oo_m += __shfl_xor_sync(0xffffffffu, oo_o, 8);
#pragma unroll
            for (int o = 1; o <= 4; o <<= 1) {
                Pam  += __shfl_xor_sync(0xffffffffu, Pam,  o);
                Pbm  += __shfl_xor_sync(0xffffffffu, Pbm,  o);
                G1m  += __shfl_xor_sync(0xffffffffu, G1m,  o);
                oo_m += __shfl_xor_sync(0xffffffffu, oo_m, o);
            }

            // prev token's o2 store (deferred)
            if (T != 0 && (p & 7) == 0)
                obase[(size_t)(T - 1) * v_stride + osel] = oo_m;

            // scalar chain (own column)
            const float2 v1f = *reinterpret_cast<const float2*>(&sv[buf][s1][c2 * 2]);
            const float2 v2f = *reinterpret_cast<const float2*>(&sv[buf][s2][c2 * 2]);
            const float v1o = lowp ? v1f.x : v1f.y;
            const float v2o = lowp ? v2f.x : v2f.y;

            const float u1 = b1 * (v1o - e1 * Pam);
            const float k2S1 = e1 * Pbm + cr.x * u1;
            const float u2 = b2 * (v2o - e2 * k2S1);
            const float o1 = e1 * G1m + cr.y * u1;
            if ((p & 7) == 0)
                obase[(size_t)T * v_stride + osel] = o1;

            // coeff exchange (other column's u's)
            const float e12 = e1 * e2;
            const float c1 = e2 * u1;
            const float c1x = __shfl_xor_sync(0xffffffffu, c1, 8);
            const float u2x = __shfl_xor_sync(0xffffffffu, u2, 8);

            // owned update (overlaps the exchange)
            const ull ep  = pack2(e12, e12);
            const ull c1p = pack2(c1, c1), u2p = pack2(u2, u2);
            MUL2(so[0], so[0], ep); FMA2(so[0], k1a.u[0], c1p, so[0]); FMA2(so[0], k2a.u[0], u2p, so[0]);
            MUL2(so[1], so[1], ep); FMA2(so[1], k1a.u[1], c1p, so[1]); FMA2(so[1], k2a.u[1], u2p, so[1]);
            MUL2(so[2], so[2], ep); FMA2(so[2], k1b.u[0], c1p, so[2]); FMA2(so[2], k2b.u[0], u2p, so[2]);
            MUL2(so[3], so[3], ep); FMA2(so[3], k1b.u[1], c1p, so[3]); FMA2(so[3], k2b.u[1], u2p, so[3]);

            const ull c1xp = pack2(c1x, c1x), u2xp = pack2(u2x, u2x);
            MUL2(sx[0], sx[0], ep); FMA2(sx[0], k1a.u[0], c1xp, sx[0]); FMA2(sx[0], k2a.u[0], u2xp, sx[0]);
            MUL2(sx[1], sx[1], ep); FMA2(sx[1], k1a.u[1], c1xp, sx[1]); FMA2(sx[1], k2a.u[1], u2xp, sx[1]);
            MUL2(sx[2], sx[2], ep); FMA2(sx[2], k1b.u[0], c1xp, sx[2]); FMA2(sx[2], k2b.u[0], u2xp, sx[2]);
            MUL2(sx[3], sx[3], ep); FMA2(sx[3], k1b.u[1], c1xp, sx[3]); FMA2(sx[3], k2b.u[1], u2xp, sx[3]);

            // deferred o2 partials: q2 . S2
            {
                F4U q2a, q2b;
                const float* r4 = &sq[buf][s2][0];
                q2a.f = *reinterpret_cast<const float4*>(r4 + p * 4);
                q2b.f = *reinterpret_cast<const float4*>(r4 + 64 + p * 4);
                ull qo = 0, qx = 0;
                FMA2(qo, q2a.u[0], so[0], qo); FMA2(qx, q2a.u[0], sx[0], qx);
                FMA2(qo, q2a.u[1], so[1], qo); FMA2(qx, q2a.u[1], sx[1], qx);
                FMA2(qo, q2b.u[0], so[2], qo); FMA2(qx, q2b.u[0], sx[2], qx);
                FMA2(qo, q2b.u[1], so[3], qo); FMA2(qx, q2b.u[1], sx[3], qx);
                oo_m = sum2(qo);
                oo_o = sum2(qx);
            }
        }

        cpa_wait0();
        __syncthreads();
        buf ^= 1;
    }

    // drain: reduce and store the final token's o2
    {
        oo_m += __shfl_xor_sync(0xffffffffu, oo_o, 8);
        oo_m += __shfl_xor_sync(0xffffffffu, oo_m, 1);
        oo_m += __shfl_xor_sync(0xffffffffu, oo_m, 2);
        oo_m += __shfl_xor_sync(0xffffffffu, oo_m, 4);
        if ((p & 7) == 0)
            obase[(size_t)(S_LEN - 1) * v_stride + osel] = oo_m;
    }
}

// ---------------- launch ----------------
extern "C" void kernel_launch(void* const* d_in, const int* in_sizes, int n_in,
                              void* d_out, int out_size)
{
    const float* mixed_qkv = (const float*)d_in[0];
    const float* bvec      = (const float*)d_in[1];
    const float* avec      = (const float*)d_in[2];
    const float* convw     = (const float*)d_in[3];
    const float* dt_bias   = (const float*)d_in[4];
    const float* alog      = (const float*)d_in[5];
    float* out = (float*)d_out;

    prep_kernel<<<2048, 256>>>(mixed_qkv, convw);
    cross_kernel<<<BQ * HK * (S_LEN / 2) / 8, 256>>>();
    gate_kernel<<<NROWS * HV / 256, 256>>>(bvec, avec, dt_bias, alog);
    rec_kernel<<<BQ * HV * 2, 512>>>(out);
}